// round 1
// baseline (speedup 1.0000x reference)
#include <cuda_runtime.h>
#include <math.h>

#define A_NUM   9
#define H_      128
#define W_      192
#define HW      (H_ * W_)          // 24576
#define N_ANCH  (A_NUM * HW)       // 221184
#define PRE_NMS 6000
#define POST_NMS 300
#define CAP     8192
#define NBIN    2048
#define NMS_TH  0.7f

// ---------------- device scratch (no allocs allowed) ----------------
__device__ float4 g_props[N_ANCH];                 // boxes in [a][pos] layout
__device__ float  g_score[N_ANCH];                 // masked score (-inf invalid)
__device__ int    g_hist[NBIN];
__device__ int    g_bstar;
__device__ int    g_count;
__device__ unsigned long long g_compact[CAP];

// anchors_base from _generate_anchors(), exact fp32 values (verified by hand,
// numpy banker's rounding included): order = ratio-major (0.5,1,2), scale-minor (8,16,32)
__constant__ float c_anchors[9][4] = {
    { -84.f,  -40.f,  99.f,  55.f},
    {-176.f,  -88.f, 191.f, 103.f},
    {-360.f, -184.f, 375.f, 199.f},
    { -56.f,  -56.f,  71.f,  71.f},
    {-120.f, -120.f, 135.f, 135.f},
    {-248.f, -248.f, 263.f, 263.f},
    { -36.f,  -80.f,  51.f,  95.f},
    { -80.f, -168.f,  95.f, 183.f},
    {-168.f, -344.f, 183.f, 359.f}
};

__global__ void init_kernel() {
    int t = blockIdx.x * blockDim.x + threadIdx.x;
    if (t < NBIN) g_hist[t] = 0;
}

// ---------------- decode + validity + histogram ----------------
__global__ void decode_kernel(const float* __restrict__ scores,
                              const float* __restrict__ deltas,
                              const float* __restrict__ iminfo) {
    __shared__ int sh[NBIN];
    for (int i = threadIdx.x; i < NBIN; i += blockDim.x) sh[i] = 0;
    __syncthreads();

    int t = blockIdx.x * blockDim.x + threadIdx.x;
    if (t < N_ANCH) {
        int a = t / HW;
        int pos = t - a * HW;
        int x = pos % W_, y = pos / W_;

        float s  = scores[(A_NUM + a) * HW + pos];
        float dx = deltas[(4 * a + 0) * HW + pos];
        float dy = deltas[(4 * a + 1) * HW + pos];
        float dw = deltas[(4 * a + 2) * HW + pos];
        float dh = deltas[(4 * a + 3) * HW + pos];
        dw = fminf(fmaxf(dw, -10.f), 10.f);
        dh = fminf(fmaxf(dh, -10.f), 10.f);

        float sx = (float)(x * 16), sy = (float)(y * 16);
        float ax1 = c_anchors[a][0] + sx;
        float ay1 = c_anchors[a][1] + sy;
        float ax2 = c_anchors[a][2] + sx;
        float ay2 = c_anchors[a][3] + sy;

        float wdt = ax2 - ax1 + 1.0f;
        float hgt = ay2 - ay1 + 1.0f;
        float cx  = ax1 + 0.5f * wdt;
        float cy  = ay1 + 0.5f * hgt;

        float pcx = dx * wdt + cx;
        float pcy = dy * hgt + cy;
        float pw  = expf(dw) * wdt;
        float ph  = expf(dh) * hgt;

        float x1 = pcx - 0.5f * pw;
        float y1 = pcy - 0.5f * ph;
        float x2 = pcx + 0.5f * pw;
        float y2 = pcy + 0.5f * ph;

        float hm = iminfo[0] - 1.0f;   // H*stride - 1
        float wm = iminfo[1] - 1.0f;   // W*stride - 1
        x1 = fminf(fmaxf(x1, 0.f), wm);
        x2 = fminf(fmaxf(x2, 0.f), wm);
        y1 = fminf(fmaxf(y1, 0.f), hm);
        y2 = fminf(fmaxf(y2, 0.f), hm);

        float msz = 16.0f * iminfo[2];
        bool valid = (x2 - x1 + 1.0f >= msz) && (y2 - y1 + 1.0f >= msz);

        g_props[t] = make_float4(x1, y1, x2, y2);
        g_score[t] = valid ? s : __int_as_float(0xff800000);  // -inf

        if (valid) {
            int bin = (int)(s * (float)NBIN);
            bin = min(max(bin, 0), NBIN - 1);
            atomicAdd(&sh[bin], 1);
        }
    }
    __syncthreads();
    for (int i = threadIdx.x; i < NBIN; i += blockDim.x)
        if (sh[i]) atomicAdd(&g_hist[i], sh[i]);
}

// ---------------- find threshold bin, reset counter ----------------
__global__ void select_kernel() {
    __shared__ int h[NBIN];
    for (int i = threadIdx.x; i < NBIN; i += blockDim.x) h[i] = g_hist[i];
    __syncthreads();
    if (threadIdx.x == 0) {
        int cum = 0, bstar = 0;
        for (int b = NBIN - 1; b >= 0; --b) {
            cum += h[b];
            if (cum >= PRE_NMS) { bstar = b; break; }
        }
        g_bstar = bstar;
        g_count = 0;
    }
}

// ---------------- compact candidates above threshold ----------------
__global__ void compact_kernel() {
    int t = blockIdx.x * blockDim.x + threadIdx.x;
    if (t >= N_ANCH) return;
    float s = g_score[t];
    if (!(s >= 0.0f)) return;   // invalid => -inf (scores are uniform in [0,1))
    int bin = (int)(s * (float)NBIN);
    bin = min(max(bin, 0), NBIN - 1);
    if (bin < g_bstar) return;
    int pos = atomicAdd(&g_count, 1);
    if (pos < CAP) {
        unsigned u = __float_as_uint(s) | 0x80000000u;   // order-preserving (s >= 0)
        int a = t / HW, p = t - a * HW;
        unsigned refIdx = (unsigned)(p * A_NUM + a);     // reference flat index
        // descending sort on (score, smaller-index-first) => secondary key = ~index
        g_compact[pos] = ((unsigned long long)u << 32) | (unsigned)(~refIdx);
    }
}

// ---------------- sort + greedy NMS + output (single block) ----------------
__global__ void __launch_bounds__(512, 1)
sort_nms_kernel(float* __restrict__ out) {
    extern __shared__ unsigned long long sortbuf[];   // CAP * 8 = 64KB
    __shared__ float4 keptBox[POST_NMS];
    __shared__ float  keptArea[POST_NMS];
    __shared__ float4 candBox[32];
    __shared__ float  candArea[32];
    __shared__ unsigned earlier[32];
    __shared__ unsigned shSupp;
    __shared__ unsigned candValidMask;
    __shared__ int shKept;
    __shared__ int shStop;

    const int T = 512;
    int tid = threadIdx.x;

    int n = g_count;
    if (n > CAP) n = CAP;
    for (int i = tid; i < CAP; i += T)
        sortbuf[i] = (i < n) ? g_compact[i] : 0ull;
    __syncthreads();

    // bitonic sort, descending (keys are unique: index embedded)
    for (int k = 2; k <= CAP; k <<= 1) {
        for (int j = k >> 1; j > 0; j >>= 1) {
            for (int i = tid; i < CAP; i += T) {
                int ixj = i ^ j;
                if (ixj > i) {
                    unsigned long long va = sortbuf[i], vb = sortbuf[ixj];
                    bool up = ((i & k) == 0);
                    if (up ? (va < vb) : (va > vb)) {
                        sortbuf[i] = vb;
                        sortbuf[ixj] = va;
                    }
                }
            }
            __syncthreads();
        }
    }

    if (tid == 0) { shKept = 0; shStop = 0; }
    __syncthreads();

    // greedy NMS, 32 candidates per batch, early stop at 300 kept
    for (int base = 0; base < PRE_NMS; base += 32) {
        int bcount = min(32, PRE_NMS - base);
        if (tid == 0) shSupp = 0u;
        if (tid < 32) {
            bool v = false;
            float4 b = make_float4(0.f, 0.f, 0.f, 0.f);
            if (tid < bcount) {
                unsigned long long key = sortbuf[base + tid];
                if ((unsigned)(key >> 32) != 0u) {
                    unsigned refIdx = ~((unsigned)key);
                    unsigned a = refIdx % A_NUM, p = refIdx / A_NUM;
                    b = g_props[a * HW + p];
                    v = true;
                }
            }
            candBox[tid] = b;
            candArea[tid] = (b.z - b.x) * (b.w - b.y);
            unsigned vm = __ballot_sync(0xffffffffu, v);
            if (tid == 0) candValidMask = vm;
        }
        __syncthreads();

        int kc = shKept;
        if (tid < 480) {                 // warps 0..14: candidates vs kept list
            unsigned m = 0u;
            if (tid < kc) {
                float4 kb = keptBox[tid];
                float  ka = keptArea[tid];
                #pragma unroll 8
                for (int c = 0; c < 32; ++c) {
                    float4 cb = candBox[c];
                    float lx = fmaxf(kb.x, cb.x);
                    float ly = fmaxf(kb.y, cb.y);
                    float rx = fminf(kb.z, cb.z);
                    float ry = fminf(kb.w, cb.w);
                    float w = fmaxf(rx - lx, 0.f);
                    float h = fmaxf(ry - ly, 0.f);
                    float inter = w * h;
                    float iou = inter / (ka + candArea[c] - inter);
                    if (iou > NMS_TH) m |= (1u << c);
                }
            }
            unsigned wOr = __reduce_or_sync(0xffffffffu, m);
            if ((tid & 31) == 0 && wOr) atomicOr(&shSupp, wOr);
        } else {                         // warp 15: intra-batch triangle
            int c = tid - 480;
            float4 cb = candBox[c];
            float  ca = candArea[c];
            unsigned e = 0u;
            for (int jj = 0; jj < c; ++jj) {
                float4 jb = candBox[jj];
                float lx = fmaxf(jb.x, cb.x);
                float ly = fmaxf(jb.y, cb.y);
                float rx = fminf(jb.z, cb.z);
                float ry = fminf(jb.w, cb.w);
                float w = fmaxf(rx - lx, 0.f);
                float h = fmaxf(ry - ly, 0.f);
                float inter = w * h;
                float iou = inter / (candArea[jj] + ca - inter);
                if (iou > NMS_TH) e |= (1u << jj);
            }
            earlier[c] = e;
        }
        __syncthreads();

        if (tid == 0) {                  // serial resolve within batch
            unsigned supp = shSupp, vm = candValidMask;
            int kcnt = shKept;
            unsigned newKeep = 0u;
            for (int c = 0; c < bcount; ++c) {
                if (kcnt >= POST_NMS) break;
                if (!((vm >> c) & 1u)) continue;
                if ((supp >> c) & 1u) continue;
                if (earlier[c] & newKeep) continue;
                newKeep |= (1u << c);
                keptBox[kcnt]  = candBox[c];
                keptArea[kcnt] = candArea[c];
                kcnt++;
            }
            shKept = kcnt;
            if (kcnt >= POST_NMS) shStop = 1;
        }
        __syncthreads();
        if (shStop) break;
    }

    int kcf = shKept;
    for (int k = tid; k < POST_NMS; k += T) {
        float4 b = (k < kcf) ? keptBox[k] : make_float4(0.f, 0.f, 0.f, 0.f);
        out[k * 5 + 0] = 0.0f;
        out[k * 5 + 1] = b.x;
        out[k * 5 + 2] = b.y;
        out[k * 5 + 3] = b.z;
        out[k * 5 + 4] = b.w;
    }
}

extern "C" void kernel_launch(void* const* d_in, const int* in_sizes, int n_in,
                              void* d_out, int out_size) {
    const float* scores = (const float*)d_in[0];
    const float* deltas = (const float*)d_in[1];
    const float* iminfo = (const float*)d_in[2];
    float* out = (float*)d_out;

    cudaFuncSetAttribute(sort_nms_kernel,
                         cudaFuncAttributeMaxDynamicSharedMemorySize, CAP * 8);

    init_kernel<<<(NBIN + 255) / 256, 256>>>();
    decode_kernel<<<(N_ANCH + 255) / 256, 256>>>(scores, deltas, iminfo);
    select_kernel<<<1, 256>>>();
    compact_kernel<<<(N_ANCH + 255) / 256, 256>>>();
    sort_nms_kernel<<<1, 512, CAP * 8>>>(out);
}

// round 2
// speedup vs baseline: 1.8262x; 1.8262x over previous
#include <cuda_runtime.h>
#include <math.h>

#define A_NUM   9
#define H_      128
#define W_      192
#define HW      (H_ * W_)          // 24576
#define N_ANCH  (A_NUM * HW)       // 221184
#define PRE_NMS 6000
#define POST_NMS 300
#define NBIN    2048
#define SCAP    16384
#define BCAP    1024
#define NMS_TH  0.7f

// ---------------- device scratch ----------------
__device__ float4 g_props[N_ANCH];                 // boxes, [a][pos] layout
__device__ float  g_score[N_ANCH];                 // masked score (-inf invalid)
__device__ int    g_hist[NBIN];
__device__ int    g_off[NBIN];                     // descending-order segment start
__device__ int    g_bincnt[NBIN];
__device__ int    g_bstar;
__device__ int    g_total;
__device__ unsigned long long g_sorted[SCAP];

// anchors_base from _generate_anchors(), exact fp32 values
__constant__ float c_anchors[9][4] = {
    { -84.f,  -40.f,  99.f,  55.f},
    {-176.f,  -88.f, 191.f, 103.f},
    {-360.f, -184.f, 375.f, 199.f},
    { -56.f,  -56.f,  71.f,  71.f},
    {-120.f, -120.f, 135.f, 135.f},
    {-248.f, -248.f, 263.f, 263.f},
    { -36.f,  -80.f,  51.f,  95.f},
    { -80.f, -168.f,  95.f, 183.f},
    {-168.f, -344.f, 183.f, 359.f}
};

__global__ void init_kernel() {
    int t = blockIdx.x * blockDim.x + threadIdx.x;
    if (t < NBIN) { g_hist[t] = 0; g_bincnt[t] = 0; }
}

// ---------------- decode + validity + histogram ----------------
__global__ void decode_kernel(const float* __restrict__ scores,
                              const float* __restrict__ deltas,
                              const float* __restrict__ iminfo) {
    __shared__ int sh[NBIN];
    for (int i = threadIdx.x; i < NBIN; i += blockDim.x) sh[i] = 0;
    __syncthreads();

    int t = blockIdx.x * blockDim.x + threadIdx.x;
    if (t < N_ANCH) {
        int a = t / HW;
        int pos = t - a * HW;
        int x = pos % W_, y = pos / W_;

        float s  = scores[(A_NUM + a) * HW + pos];
        float dx = deltas[(4 * a + 0) * HW + pos];
        float dy = deltas[(4 * a + 1) * HW + pos];
        float dw = deltas[(4 * a + 2) * HW + pos];
        float dh = deltas[(4 * a + 3) * HW + pos];
        dw = fminf(fmaxf(dw, -10.f), 10.f);
        dh = fminf(fmaxf(dh, -10.f), 10.f);

        float sx = (float)(x * 16), sy = (float)(y * 16);
        float ax1 = c_anchors[a][0] + sx;
        float ay1 = c_anchors[a][1] + sy;
        float ax2 = c_anchors[a][2] + sx;
        float ay2 = c_anchors[a][3] + sy;

        float wdt = ax2 - ax1 + 1.0f;
        float hgt = ay2 - ay1 + 1.0f;
        float cx  = ax1 + 0.5f * wdt;
        float cy  = ay1 + 0.5f * hgt;

        float pcx = dx * wdt + cx;
        float pcy = dy * hgt + cy;
        float pw  = expf(dw) * wdt;
        float ph  = expf(dh) * hgt;

        float x1 = pcx - 0.5f * pw;
        float y1 = pcy - 0.5f * ph;
        float x2 = pcx + 0.5f * pw;
        float y2 = pcy + 0.5f * ph;

        float hm = iminfo[0] - 1.0f;
        float wm = iminfo[1] - 1.0f;
        x1 = fminf(fmaxf(x1, 0.f), wm);
        x2 = fminf(fmaxf(x2, 0.f), wm);
        y1 = fminf(fmaxf(y1, 0.f), hm);
        y2 = fminf(fmaxf(y2, 0.f), hm);

        float msz = 16.0f * iminfo[2];
        bool valid = (x2 - x1 + 1.0f >= msz) && (y2 - y1 + 1.0f >= msz);

        g_props[t] = make_float4(x1, y1, x2, y2);
        g_score[t] = valid ? s : __int_as_float(0xff800000);

        if (valid) {
            int bin = min((int)(s * (float)NBIN), NBIN - 1);
            atomicAdd(&sh[max(bin, 0)], 1);
        }
    }
    __syncthreads();
    for (int i = threadIdx.x; i < NBIN; i += blockDim.x)
        if (sh[i]) atomicAdd(&g_hist[i], sh[i]);
}

// ---------------- suffix scan over bins, threshold, segment offsets ----------------
__global__ void scan_kernel() {
    __shared__ int shTot[16];
    __shared__ int shAbove[16];
    __shared__ int shSuff[NBIN];
    int tid = threadIdx.x;                 // 512 threads, 4 bins each
    int h0 = g_hist[4 * tid + 0];
    int h1 = g_hist[4 * tid + 1];
    int h2 = g_hist[4 * tid + 2];
    int h3 = g_hist[4 * tid + 3];
    int chunk = h0 + h1 + h2 + h3;

    int lane = tid & 31, w = tid >> 5;
    int v = chunk;
    #pragma unroll
    for (int d = 1; d < 32; d <<= 1) {     // suffix-inclusive scan within warp
        int o = __shfl_down_sync(0xffffffffu, v, d);
        if (lane + d < 32) v += o;
    }
    if (lane == 0) shTot[w] = v;
    __syncthreads();
    if (tid < 16) {
        int tot = shTot[tid];
        int s = tot;
        #pragma unroll
        for (int d = 1; d < 16; d <<= 1) {
            int o = __shfl_down_sync(0x0000ffffu, s, d, 16);
            if (tid + d < 16) s += o;
        }
        shAbove[tid] = s - tot;            // sum of warps strictly after
    }
    __syncthreads();

    int suffInclChunk = v + shAbove[w];    // own chunk + everything above
    int above = suffInclChunk - chunk;
    int s3 = above + h3;
    int s2 = s3 + h2;
    int s1 = s2 + h1;
    int s0 = s1 + h0;
    shSuff[4 * tid + 0] = s0;
    shSuff[4 * tid + 1] = s1;
    shSuff[4 * tid + 2] = s2;
    shSuff[4 * tid + 3] = s3;
    g_off[4 * tid + 0] = s0 - h0;          // exclusive: items strictly above bin
    g_off[4 * tid + 1] = s1 - h1;
    g_off[4 * tid + 2] = s2 - h2;
    g_off[4 * tid + 3] = s3 - h3;
    __syncthreads();

    if (tid == 0) {
        int b = NBIN - 1;
        while (b > 0 && shSuff[b] < PRE_NMS) --b;
        g_bstar = b;
        g_total = shSuff[b];
    }
}

// ---------------- scatter candidates into bin segments ----------------
__global__ void scatter_kernel() {
    int t = blockIdx.x * blockDim.x + threadIdx.x;
    if (t >= N_ANCH) return;
    float s = g_score[t];
    if (!(s >= 0.0f)) return;
    int bin = min((int)(s * (float)NBIN), NBIN - 1);
    if (bin < g_bstar) return;
    int slot = g_off[bin] + atomicAdd(&g_bincnt[bin], 1);
    if (slot < SCAP) {
        unsigned u = __float_as_uint(s);   // s >= 0: bits are order-preserving
        int a = t / HW, p = t - a * HW;
        unsigned refIdx = (unsigned)(p * A_NUM + a);
        g_sorted[slot] = ((unsigned long long)u << 32) | (unsigned)(~refIdx);
    }
}

// ---------------- per-bin descending sort (one block per bin) ----------------
__global__ void __launch_bounds__(256)
binsort_kernel() {
    int b = blockIdx.x;
    if (b < g_bstar) return;
    int c = g_hist[b];
    if (c <= 1) return;
    if (c > BCAP) c = BCAP;                // statistically impossible (avg ~110)
    int start = g_off[b];

    __shared__ unsigned long long sb[BCAP];
    int P = 1;
    while (P < c) P <<= 1;
    int tid = threadIdx.x;
    for (int i = tid; i < P; i += 256)
        sb[i] = (i < c) ? g_sorted[start + i] : 0ull;
    __syncthreads();

    for (int k = 2; k <= P; k <<= 1) {
        for (int j = k >> 1; j > 0; j >>= 1) {
            for (int i = tid; i < P; i += 256) {
                int ixj = i ^ j;
                if (ixj > i) {
                    unsigned long long va = sb[i], vb = sb[ixj];
                    bool up = ((i & k) == 0);      // descending overall
                    if (up ? (va < vb) : (va > vb)) {
                        sb[i] = vb;
                        sb[ixj] = va;
                    }
                }
            }
            __syncthreads();
        }
    }
    for (int i = tid; i < c; i += 256) g_sorted[start + i] = sb[i];
}

// ---------------- greedy NMS (single block, 64 candidates / round) ----------------
__global__ void __launch_bounds__(512, 1)
nms_kernel(float* __restrict__ out) {
    __shared__ float4 keptBox[POST_NMS];
    __shared__ float  keptArea[POST_NMS];
    __shared__ float4 candBox[64];
    __shared__ float  candArea[64];
    __shared__ unsigned long long earlier[64];
    __shared__ unsigned long long shSupp;
    __shared__ int shKept;
    __shared__ int shStop;

    int tid = threadIdx.x;
    int ncand = min(g_total, PRE_NMS);
    if (tid == 0) { shKept = 0; shStop = 0; }
    __syncthreads();

    for (int base = 0; base < ncand; base += 64) {
        int bcount = min(64, ncand - base);
        if (tid == 0) shSupp = 0ull;
        if (tid < 64) {
            float4 b = make_float4(0.f, 0.f, 0.f, 0.f);
            if (tid < bcount) {
                unsigned long long key = g_sorted[base + tid];
                unsigned refIdx = ~((unsigned)key);
                unsigned a = refIdx % A_NUM, p = refIdx / A_NUM;
                b = g_props[a * HW + p];
            }
            candBox[tid] = b;
            candArea[tid] = (b.z - b.x) * (b.w - b.y);
        }
        __syncthreads();

        int kc = shKept;
        if (tid < 448) {                    // 14 warps: kept vs 64 candidates
            unsigned long long m = 0ull;
            if (tid < kc) {
                float4 kb = keptBox[tid];
                float  ka = keptArea[tid];
                #pragma unroll 8
                for (int c = 0; c < 64; ++c) {
                    float4 cb = candBox[c];
                    float lx = fmaxf(kb.x, cb.x);
                    float ly = fmaxf(kb.y, cb.y);
                    float rx = fminf(kb.z, cb.z);
                    float ry = fminf(kb.w, cb.w);
                    float w = fmaxf(rx - lx, 0.f);
                    float h = fmaxf(ry - ly, 0.f);
                    float inter = w * h;
                    float iou = inter / (ka + candArea[c] - inter);
                    if (iou > NMS_TH) m |= (1ull << c);
                }
            }
            #pragma unroll
            for (int d = 16; d > 0; d >>= 1)
                m |= __shfl_xor_sync(0xffffffffu, m, d);
            if ((tid & 31) == 0 && m) atomicOr(&shSupp, m);
        } else {                            // 2 warps: intra-batch triangle
            int c = tid - 448;
            float4 cb = candBox[c];
            float  ca = candArea[c];
            unsigned long long e = 0ull;
            for (int jj = 0; jj < c; ++jj) {
                float4 jb = candBox[jj];
                float lx = fmaxf(jb.x, cb.x);
                float ly = fmaxf(jb.y, cb.y);
                float rx = fminf(jb.z, cb.z);
                float ry = fminf(jb.w, cb.w);
                float w = fmaxf(rx - lx, 0.f);
                float h = fmaxf(ry - ly, 0.f);
                float inter = w * h;
                float iou = inter / (candArea[jj] + ca - inter);
                if (iou > NMS_TH) e |= (1ull << jj);
            }
            earlier[c] = e;
        }
        __syncthreads();

        if (tid == 0) {
            unsigned long long supp = shSupp;
            unsigned long long newKeep = 0ull;
            int kcnt = shKept;
            for (int c = 0; c < bcount; ++c) {
                if (kcnt >= POST_NMS) break;
                if ((supp >> c) & 1ull) continue;
                if (earlier[c] & newKeep) continue;
                newKeep |= (1ull << c);
                keptBox[kcnt]  = candBox[c];
                keptArea[kcnt] = candArea[c];
                kcnt++;
            }
            shKept = kcnt;
            if (kcnt >= POST_NMS) shStop = 1;
        }
        __syncthreads();
        if (shStop) break;
    }

    int kcf = shKept;
    for (int k = tid; k < POST_NMS; k += 512) {
        float4 b = (k < kcf) ? keptBox[k] : make_float4(0.f, 0.f, 0.f, 0.f);
        out[k * 5 + 0] = 0.0f;
        out[k * 5 + 1] = b.x;
        out[k * 5 + 2] = b.y;
        out[k * 5 + 3] = b.z;
        out[k * 5 + 4] = b.w;
    }
}

extern "C" void kernel_launch(void* const* d_in, const int* in_sizes, int n_in,
                              void* d_out, int out_size) {
    const float* scores = (const float*)d_in[0];
    const float* deltas = (const float*)d_in[1];
    const float* iminfo = (const float*)d_in[2];
    float* out = (float*)d_out;

    init_kernel<<<(NBIN + 255) / 256, 256>>>();
    decode_kernel<<<(N_ANCH + 255) / 256, 256>>>(scores, deltas, iminfo);
    scan_kernel<<<1, 512>>>();
    scatter_kernel<<<(N_ANCH + 255) / 256, 256>>>();
    binsort_kernel<<<NBIN, 256>>>();
    nms_kernel<<<1, 512>>>(out);
}